// round 5
// baseline (speedup 1.0000x reference)
#include <cuda_runtime.h>
#include <cuda_bf16.h>
#include <cstdint>

// Problem dims (fixed by the dataset)
#define BB 32
#define SS 1024
#define II 256
#define HH 512
#define OO 256
#define MROWS (BB * SS)   // 32768

// Scratch (allocation-free rule: __device__ globals)
__device__ float g_ic[(size_t)MROWS * HH];   // 64 MB input currents
__device__ float g_spk[(size_t)MROWS * HH];  // 64 MB spikes (fp32 0/1)

// ---------------------------------------------------------------------------
// Register-blocked SGEMM: C[M,N] = A[M,K] @ B[K,N], all row-major fp32.
// BM=BN=128, BK=16, TM=TN=8, 256 threads.
// ---------------------------------------------------------------------------
template <int BM, int BN, int BK, int TM, int TN>
__global__ __launch_bounds__(256) void sgemm_kernel(
    const float* __restrict__ A, const float* __restrict__ Bm,
    float* __restrict__ C, int M, int N, int K)
{
    __shared__ float As[BK][BM];
    __shared__ float Bs[BK][BN];

    const int tid = threadIdx.x;
    const int mBlock = blockIdx.y * BM;
    const int nBlock = blockIdx.x * BN;

    const int tCols = BN / TN;          // 16
    const int tRow = tid / tCols;       // 0..15
    const int tCol = tid % tCols;       // 0..15

    float acc[TM][TN];
#pragma unroll
    for (int i = 0; i < TM; i++)
#pragma unroll
        for (int j = 0; j < TN; j++) acc[i][j] = 0.f;

    for (int k0 = 0; k0 < K; k0 += BK) {
        // A tile (BM x BK), float4 along K, stored transposed
#pragma unroll
        for (int it = 0; it < (BM * BK) / (256 * 4); it++) {
            int f = tid + it * 256;
            int m = f / (BK / 4);
            int kq = f % (BK / 4);
            float4 v = *reinterpret_cast<const float4*>(
                &A[(size_t)(mBlock + m) * K + k0 + kq * 4]);
            As[kq * 4 + 0][m] = v.x;
            As[kq * 4 + 1][m] = v.y;
            As[kq * 4 + 2][m] = v.z;
            As[kq * 4 + 3][m] = v.w;
        }
        // B tile (BK x BN)
#pragma unroll
        for (int it = 0; it < (BK * BN) / (256 * 4); it++) {
            int f = tid + it * 256;
            int k = f / (BN / 4);
            int nq = f % (BN / 4);
            float4 v = *reinterpret_cast<const float4*>(
                &Bm[(size_t)(k0 + k) * N + nBlock + nq * 4]);
            *reinterpret_cast<float4*>(&Bs[k][nq * 4]) = v;
        }
        __syncthreads();

#pragma unroll
        for (int k = 0; k < BK; k++) {
            float ra[TM], rb[TN];
#pragma unroll
            for (int i = 0; i < TM; i++) ra[i] = As[k][tRow * TM + i];
#pragma unroll
            for (int j = 0; j < TN; j++) rb[j] = Bs[k][tCol * TN + j];
#pragma unroll
            for (int i = 0; i < TM; i++)
#pragma unroll
                for (int j = 0; j < TN; j++) acc[i][j] += ra[i] * rb[j];
        }
        __syncthreads();
    }

#pragma unroll
    for (int i = 0; i < TM; i++) {
        float* crow = &C[(size_t)(mBlock + tRow * TM + i) * N + nBlock + tCol * TN];
#pragma unroll
        for (int j = 0; j < TN; j += 4) {
            float4 v = make_float4(acc[i][j], acc[i][j + 1], acc[i][j + 2], acc[i][j + 3]);
            *reinterpret_cast<float4*>(&crow[j]) = v;
        }
    }
}

// ---------------------------------------------------------------------------
// Recurrent scan. One CTA per batch (32 CTAs), 1024 threads.
//   thread = (shard g = tid>>7  in 0..7,  column-quad hq = tid&127)
// Gather: lateral[h] = sum_{j in firing} W_lat[j,h], firing list in smem.
// Each shard walks list entries g, g+8, g+16, ... with a 4-deep batch of
// independent LDG.128 (MLP=4/thread, 32 warps) into 4 float4 accumulators.
// Threads 0..511 own one neuron each (state in registers).
// 3 bar.syncs per step; everything CTA-local (no cluster, no DSMEM).
// ---------------------------------------------------------------------------
__global__ __launch_bounds__(1024, 1) void snn_scan_kernel(
    const float* __restrict__ ic, const float* __restrict__ Wlat,
    const float* __restrict__ thr, float* __restrict__ spk)
{
    __shared__ float4 part4[8][128];     // [shard][hq] partial lateral (16 KB)
    __shared__ unsigned masks_s[16];
    __shared__ int list_s[HH];

    const int b = blockIdx.x;
    const int tid = threadIdx.x;           // 0..1023
    const int lane = tid & 31;
    const int warp = tid >> 5;             // 0..31
    const int g = tid >> 7;                // shard 0..7
    const int hq = tid & 127;              // float4 column group

    const float4* Wl4 = reinterpret_cast<const float4*>(Wlat);  // row j: Wl4[j*128 + hq]
    const float* partf = reinterpret_cast<const float*>(part4); // part[s*512 + h]

    const bool owner = (tid < HH);
    float mp = 0.f;
    int refrac = 0;
    int ns = 0;
    const float thrv = owner ? thr[tid] : 0.f;

    const size_t rowbase = (size_t)b * SS * HH;
    float ic_cur = owner ? ic[rowbase + tid] : 0.f;

    for (int t = 0; t < SS; ++t) {
        float ic_nxt = (owner && t < SS - 1) ? ic[rowbase + (size_t)(t + 1) * HH + tid] : 0.f;

        // --- lateral partials over this thread's shard of the firing list ---
        float4 A0 = make_float4(0.f, 0.f, 0.f, 0.f);
        float4 A1 = make_float4(0.f, 0.f, 0.f, 0.f);
        float4 A2 = make_float4(0.f, 0.f, 0.f, 0.f);
        float4 A3 = make_float4(0.f, 0.f, 0.f, 0.f);
        int k = g;
        for (; k + 24 < ns; k += 32) {
            int j0 = list_s[k];
            int j1 = list_s[k + 8];
            int j2 = list_s[k + 16];
            int j3 = list_s[k + 24];
            float4 w0 = Wl4[(size_t)j0 * (HH / 4) + hq];
            float4 w1 = Wl4[(size_t)j1 * (HH / 4) + hq];
            float4 w2 = Wl4[(size_t)j2 * (HH / 4) + hq];
            float4 w3 = Wl4[(size_t)j3 * (HH / 4) + hq];
            A0.x += w0.x; A0.y += w0.y; A0.z += w0.z; A0.w += w0.w;
            A1.x += w1.x; A1.y += w1.y; A1.z += w1.z; A1.w += w1.w;
            A2.x += w2.x; A2.y += w2.y; A2.z += w2.z; A2.w += w2.w;
            A3.x += w3.x; A3.y += w3.y; A3.z += w3.z; A3.w += w3.w;
        }
        for (; k < ns; k += 8) {
            int j0 = list_s[k];
            float4 w0 = Wl4[(size_t)j0 * (HH / 4) + hq];
            A0.x += w0.x; A0.y += w0.y; A0.z += w0.z; A0.w += w0.w;
        }
        A0.x += A1.x + A2.x + A3.x;
        A0.y += A1.y + A2.y + A3.y;
        A0.z += A1.z + A2.z + A3.z;
        A0.w += A1.w + A2.w + A3.w;
        part4[g][hq] = A0;
        __syncthreads();                                   // S1: partials visible

        if (owner) {
            float lat = 0.f;
#pragma unroll
            for (int s = 0; s < 8; ++s) lat += partf[s * HH + tid];

            // --- membrane update (reference semantics, fp32) ---
            mp = 0.95f * mp + ic_cur - lat;
            if (refrac > 0) mp = 0.f;
            refrac = (refrac > 0) ? (refrac - 1) : 0;
            bool spike = (mp >= thrv);
            spk[rowbase + (size_t)t * HH + tid] = spike ? 1.f : 0.f;
            if (spike) { mp = 0.f; refrac = 2; }

            unsigned m = __ballot_sync(0xffffffffu, spike);
            if (lane == 0) masks_s[warp] = m;
            // stash spike flag in bit for list write below (recomputed from mask)
        }
        __syncthreads();                                   // S2: masks visible

        // --- rebuild firing list from the 16 mask words ---
        unsigned w0m[16];
        int pref[16];
        int tot = 0;
#pragma unroll
        for (int w = 0; w < 16; ++w) {
            w0m[w] = masks_s[w];
            pref[w] = tot;
            tot += __popc(w0m[w]);
        }
        if (owner) {
            unsigned mw = w0m[warp];
            if (mw & (1u << lane)) {
                int pos = pref[warp] + __popc(mw & ((1u << lane) - 1u));
                list_s[pos] = tid;
            }
        }
        ns = tot;
        ic_cur = ic_nxt;
        __syncthreads();                                   // S3: list visible
    }
}

// ---------------------------------------------------------------------------
// Launch
// ---------------------------------------------------------------------------
extern "C" void kernel_launch(void* const* d_in, const int* in_sizes, int n_in,
                              void* d_out, int out_size)
{
    const float* x    = (const float*)d_in[0];  // [B,S,I]
    const float* Win  = (const float*)d_in[1];  // [I,H]
    const float* Wlat = (const float*)d_in[2];  // [H,H]
    const float* Wout = (const float*)d_in[3];  // [H,O]
    const float* thr  = (const float*)d_in[4];  // [H]
    float* out = (float*)d_out;                 // [B,S,O]

    float *ic, *spk;
    cudaGetSymbolAddress((void**)&ic, g_ic);
    cudaGetSymbolAddress((void**)&spk, g_spk);

    // GEMM1: ic = x @ Win   (32768 x 512 x 256)
    {
        dim3 grid(HH / 128, MROWS / 128);
        sgemm_kernel<128, 128, 16, 8, 8><<<grid, 256>>>(x, Win, ic, MROWS, HH, II);
    }

    // Scan: 32 CTAs x 1024 threads (one CTA per batch)
    snn_scan_kernel<<<BB, 1024>>>(ic, Wlat, thr, spk);

    // GEMM3: out = spk @ Wout   (32768 x 256 x 512)
    {
        dim3 grid(OO / 128, MROWS / 128);
        sgemm_kernel<128, 128, 16, 8, 8><<<grid, 256>>>(spk, Wout, out, MROWS, OO, HH);
    }
}

// round 6
// speedup vs baseline: 1.7083x; 1.7083x over previous
#include <cuda_runtime.h>
#include <cuda_bf16.h>
#include <cstdint>

// Problem dims (fixed by the dataset)
#define BB 32
#define SS 1024
#define II 256
#define HH 512
#define OO 256
#define MROWS (BB * SS)   // 32768

// Scratch (allocation-free rule: __device__ globals)
__device__ float g_ic[(size_t)MROWS * HH];   // 64 MB input currents
__device__ float g_spk[(size_t)MROWS * HH];  // 64 MB spikes (fp32 0/1)

// ---------------------------------------------------------------------------
// Register-blocked SGEMM: C[M,N] = A[M,K] @ B[K,N], all row-major fp32.
// BM=128, BN=64, BK=16, TM=8, TN=4, 256 threads (proven 211us config).
// ---------------------------------------------------------------------------
template <int BM, int BN, int BK, int TM, int TN>
__global__ __launch_bounds__(256) void sgemm_kernel(
    const float* __restrict__ A, const float* __restrict__ Bm,
    float* __restrict__ C, int M, int N, int K)
{
    __shared__ float As[BK][BM];
    __shared__ float Bs[BK][BN];

    const int tid = threadIdx.x;
    const int mBlock = blockIdx.y * BM;
    const int nBlock = blockIdx.x * BN;

    const int tCols = BN / TN;
    const int tRow = tid / tCols;
    const int tCol = tid % tCols;

    float acc[TM][TN];
#pragma unroll
    for (int i = 0; i < TM; i++)
#pragma unroll
        for (int j = 0; j < TN; j++) acc[i][j] = 0.f;

    for (int k0 = 0; k0 < K; k0 += BK) {
#pragma unroll
        for (int it = 0; it < (BM * BK) / (256 * 4); it++) {
            int f = tid + it * 256;
            int m = f / (BK / 4);
            int kq = f % (BK / 4);
            float4 v = *reinterpret_cast<const float4*>(
                &A[(size_t)(mBlock + m) * K + k0 + kq * 4]);
            As[kq * 4 + 0][m] = v.x;
            As[kq * 4 + 1][m] = v.y;
            As[kq * 4 + 2][m] = v.z;
            As[kq * 4 + 3][m] = v.w;
        }
#pragma unroll
        for (int it = 0; it < (BK * BN) / (256 * 4); it++) {
            int f = tid + it * 256;
            int k = f / (BN / 4);
            int nq = f % (BN / 4);
            float4 v = *reinterpret_cast<const float4*>(
                &Bm[(size_t)(k0 + k) * N + nBlock + nq * 4]);
            *reinterpret_cast<float4*>(&Bs[k][nq * 4]) = v;
        }
        __syncthreads();

#pragma unroll
        for (int k = 0; k < BK; k++) {
            float ra[TM], rb[TN];
#pragma unroll
            for (int i = 0; i < TM; i++) ra[i] = As[k][tRow * TM + i];
#pragma unroll
            for (int j = 0; j < TN; j++) rb[j] = Bs[k][tCol * TN + j];
#pragma unroll
            for (int i = 0; i < TM; i++)
#pragma unroll
                for (int j = 0; j < TN; j++) acc[i][j] += ra[i] * rb[j];
        }
        __syncthreads();
    }

#pragma unroll
    for (int i = 0; i < TM; i++) {
        float* crow = &C[(size_t)(mBlock + tRow * TM + i) * N + nBlock + tCol * TN];
#pragma unroll
        for (int j = 0; j < TN; j += 4) {
            float4 v = make_float4(acc[i][j], acc[i][j + 1], acc[i][j + 2], acc[i][j + 3]);
            *reinterpret_cast<float4*>(&crow[j]) = v;
        }
    }
}

// ---------------------------------------------------------------------------
// Recurrent scan. One CTA per batch (32 CTAs), 512 threads (one per neuron).
//   thread = (shard g = tid>>7 in 0..3, column-quad hq = tid&127)
// lateral[h] = sum_{j in firing} W_lat[j,h]; firing list in smem.
// Gather: 4-deep batch of INDEPENDENT LDG.128 per iteration (MLP=4/thread)
// into 4 separate float4 accumulators -> covers L2 latency (~248cyc); the
// remaining bound is the L1 wavefront rate (ns x 16 x 128B per step).
// 512 threads => 128 regs/thread available, no spills (R5 lesson).
// ---------------------------------------------------------------------------
__global__ __launch_bounds__(512, 1) void snn_scan_kernel(
    const float* __restrict__ ic, const float* __restrict__ Wlat,
    const float* __restrict__ thr, float* __restrict__ spk)
{
    __shared__ float4 part4[4][128];     // [shard][hq] partial lateral (8 KB)
    __shared__ unsigned masks_s[16];
    __shared__ int list_s[HH];

    const int b = blockIdx.x;
    const int tid = threadIdx.x;           // 0..511
    const int lane = tid & 31;
    const int warp = tid >> 5;             // 0..15
    const int g = tid >> 7;                // shard 0..3
    const int hq = tid & 127;              // float4 column group

    const float4* Wl4 = reinterpret_cast<const float4*>(Wlat);  // row j: Wl4[j*128 + hq]
    const float* partf = reinterpret_cast<const float*>(part4);

    float mp = 0.f;
    int refrac = 0;
    int ns = 0;
    const float thrv = thr[tid];

    const size_t rowbase = (size_t)b * SS * HH;
    float ic_cur = ic[rowbase + tid];

    for (int t = 0; t < SS; ++t) {
        float ic_nxt = (t < SS - 1) ? ic[rowbase + (size_t)(t + 1) * HH + tid] : 0.f;

        // --- lateral partials: 4-deep independent-load batches ---
        float4 A0 = make_float4(0.f, 0.f, 0.f, 0.f);
        float4 A1 = make_float4(0.f, 0.f, 0.f, 0.f);
        float4 A2 = make_float4(0.f, 0.f, 0.f, 0.f);
        float4 A3 = make_float4(0.f, 0.f, 0.f, 0.f);
        int k = g;
        for (; k + 12 < ns; k += 16) {
            int j0 = list_s[k];
            int j1 = list_s[k + 4];
            int j2 = list_s[k + 8];
            int j3 = list_s[k + 12];
            float4 w0 = Wl4[(size_t)j0 * (HH / 4) + hq];
            float4 w1 = Wl4[(size_t)j1 * (HH / 4) + hq];
            float4 w2 = Wl4[(size_t)j2 * (HH / 4) + hq];
            float4 w3 = Wl4[(size_t)j3 * (HH / 4) + hq];
            A0.x += w0.x; A0.y += w0.y; A0.z += w0.z; A0.w += w0.w;
            A1.x += w1.x; A1.y += w1.y; A1.z += w1.z; A1.w += w1.w;
            A2.x += w2.x; A2.y += w2.y; A2.z += w2.z; A2.w += w2.w;
            A3.x += w3.x; A3.y += w3.y; A3.z += w3.z; A3.w += w3.w;
        }
        for (; k < ns; k += 4) {
            int j0 = list_s[k];
            float4 w0 = Wl4[(size_t)j0 * (HH / 4) + hq];
            A0.x += w0.x; A0.y += w0.y; A0.z += w0.z; A0.w += w0.w;
        }
        A0.x += A1.x + A2.x + A3.x;
        A0.y += A1.y + A2.y + A3.y;
        A0.z += A1.z + A2.z + A3.z;
        A0.w += A1.w + A2.w + A3.w;
        part4[g][hq] = A0;
        __syncthreads();                                   // S1: partials visible

        // --- membrane update (reference semantics, fp32) ---
        float lat = partf[0 * HH + tid] + partf[1 * HH + tid] +
                    partf[2 * HH + tid] + partf[3 * HH + tid];
        mp = 0.95f * mp + ic_cur - lat;
        if (refrac > 0) mp = 0.f;
        refrac = (refrac > 0) ? (refrac - 1) : 0;
        bool spike = (mp >= thrv);
        spk[rowbase + (size_t)t * HH + tid] = spike ? 1.f : 0.f;
        if (spike) { mp = 0.f; refrac = 2; }

        // --- rebuild firing list (ballots + prefix over 16 words) ---
        unsigned m = __ballot_sync(0xffffffffu, spike);
        if (lane == 0) masks_s[warp] = m;
        __syncthreads();                                   // S2: masks visible

        int tot = 0, base = 0;
#pragma unroll
        for (int w = 0; w < 16; ++w) {
            if (w == warp) base = tot;
            tot += __popc(masks_s[w]);
        }
        if (spike) {
            int pos = base + __popc(m & ((1u << lane) - 1u));
            list_s[pos] = tid;
        }
        ns = tot;
        ic_cur = ic_nxt;
        __syncthreads();                                   // S3: list visible
    }
}

// ---------------------------------------------------------------------------
// Launch
// ---------------------------------------------------------------------------
extern "C" void kernel_launch(void* const* d_in, const int* in_sizes, int n_in,
                              void* d_out, int out_size)
{
    const float* x    = (const float*)d_in[0];  // [B,S,I]
    const float* Win  = (const float*)d_in[1];  // [I,H]
    const float* Wlat = (const float*)d_in[2];  // [H,H]
    const float* Wout = (const float*)d_in[3];  // [H,O]
    const float* thr  = (const float*)d_in[4];  // [H]
    float* out = (float*)d_out;                 // [B,S,O]

    float *ic, *spk;
    cudaGetSymbolAddress((void**)&ic, g_ic);
    cudaGetSymbolAddress((void**)&spk, g_spk);

    // GEMM1: ic = x @ Win   (32768 x 512 x 256)
    {
        dim3 grid(HH / 64, MROWS / 128);
        sgemm_kernel<128, 64, 16, 8, 4><<<grid, 256>>>(x, Win, ic, MROWS, HH, II);
    }

    // Scan: 32 CTAs x 512 threads (one CTA per batch)
    snn_scan_kernel<<<BB, 512>>>(ic, Wlat, thr, spk);

    // GEMM3: out = spk @ Wout   (32768 x 256 x 512)
    {
        dim3 grid(OO / 64, MROWS / 128);
        sgemm_kernel<128, 64, 16, 8, 4><<<grid, 256>>>(spk, Wout, out, MROWS, OO, HH);
    }
}